// round 15
// baseline (speedup 1.0000x reference)
#include <cuda_runtime.h>
#include <math.h>

#define N    64
#define LD   68            // padded leading dim (floats); 16B-aligned rows
#define NT   256
#define WPB  9             // warps (= matrices) per block in batch/apply kernels
#define NTB  (WPB*32)      // 288 threads: 288*216 regs = 62.2K <= 64K (no spill)
#define TILE (N*LD)        // 4352 floats
#define MAXB 8192

typedef unsigned long long u64;

// ----------------------------------------------------------------------------
// f32x2 packed helpers (sm_103a packed FP32 pipe; only reachable via PTX)
// ----------------------------------------------------------------------------
__device__ __forceinline__ u64 pk2(float lo, float hi) {
    u64 r; asm("mov.b64 %0,{%1,%2};" : "=l"(r) : "f"(lo), "f"(hi)); return r;
}
__device__ __forceinline__ void up2(u64 v, float& lo, float& hi) {
    asm("mov.b64 {%0,%1},%2;" : "=f"(lo), "=f"(hi) : "l"(v));
}
__device__ __forceinline__ u64 fma2(u64 a, u64 b, u64 c) {
    u64 r; asm("fma.rn.f32x2 %0,%1,%2,%3;" : "=l"(r) : "l"(a), "l"(b), "l"(c)); return r;
}
__device__ __forceinline__ u64 mul2(u64 a, u64 b) {
    u64 r; asm("mul.rn.f32x2 %0,%1,%2;" : "=l"(r) : "l"(a), "l"(b)); return r;
}
__device__ __forceinline__ u64 add2(u64 a, u64 b) {
    u64 r; asm("add.rn.f32x2 %0,%1,%2;" : "=l"(r) : "l"(a), "l"(b)); return r;
}

// Fast rotation scalars (MUFU approx; Jacobi self-corrects ulp-level errors)
__device__ __forceinline__ void rot_cs(float na, float nb, float d,
                                       float& c, float& s) {
    float ta = __fdividef(nb - na, 2.0f * d);
    float h  = fmaf(ta, ta, 1.0f);
    float t  = copysignf(1.0f, ta) * __fdividef(1.0f, fabsf(ta) + h * rsqrtf(h));
    c = rsqrtf(fmaf(t, t, 1.0f));
    s = t * c;
}

// ----------------------------------------------------------------------------
// Global scratch
// ----------------------------------------------------------------------------
__device__ float g_M  [N*N];
__device__ float g_Ms [N*N];
__device__ float g_Mis[N*N];
__device__ float g_L  [N*N];
__device__ float g_Ct [N*N];                   // C^T row-major (= C columns as rows)
__device__ float g_VM [N*N];                   // warm-start eigvecs of M (row-major [k][c])
__device__ float g_VL [N*N];                   // warm-start eigvecs of L+sI
__device__ float g_scratch[(size_t)MAXB*N*N];  // per-matrix logm
__device__ float g_Vw     [(size_t)MAXB*N*N];  // per-matrix eigvecs, row-major [k][c]
__device__ float g_partial[(MAXB/32)*N*N];

// ----------------------------------------------------------------------------
// Packed one-sided (Hestenes) Jacobi, odd-even ordering. Lane l holds columns
// at positions 2l (A) and 2l+1 (B); each column = 32 packed f32x2 values.
// Sweep exit: when a full sweep saw NO pair with d^2 > tiny*nA*nB.
// ----------------------------------------------------------------------------
__device__ __forceinline__ void hestenes_p(u64 (&A)[32], u64 (&B)[32],
                                           int lane, int max_sweeps,
                                           float thr, float tiny) {
    const unsigned FULL = 0xffffffffu;
    for (int sweep = 0; sweep < max_sweeps; ++sweep) {
        float nA, nB;
        {
            u64 a0=0ull,a1=0ull,a2=0ull,a3=0ull, b0=0ull,b1=0ull,b2=0ull,b3=0ull;
#pragma unroll
            for (int i = 0; i < 32; i += 4) {
                a0 = fma2(A[i],   A[i],   a0);
                a1 = fma2(A[i+1], A[i+1], a1);
                a2 = fma2(A[i+2], A[i+2], a2);
                a3 = fma2(A[i+3], A[i+3], a3);
                b0 = fma2(B[i],   B[i],   b0);
                b1 = fma2(B[i+1], B[i+1], b1);
                b2 = fma2(B[i+2], B[i+2], b2);
                b3 = fma2(B[i+3], B[i+3], b3);
            }
            u64 sa = add2(add2(a0,a1), add2(a2,a3));
            u64 sb = add2(add2(b0,b1), add2(b2,b3));
            float x0,x1,y0,y1; up2(sa,x0,x1); up2(sb,y0,y1);
            nA = x0+x1; nB = y0+y1;
        }
        int big = 0;   // per-lane: saw any pair above the tiny threshold
        for (int rr = 0; rr < 32; ++rr) {
            // ---- even round: pair (A,B) within lane ----
            {
                u64 c0=0ull,c1_=0ull,c2_=0ull,c3=0ull;
#pragma unroll
                for (int i = 0; i < 32; i += 4) {
                    c0  = fma2(A[i],   B[i],   c0);
                    c1_ = fma2(A[i+1], B[i+1], c1_);
                    c2_ = fma2(A[i+2], B[i+2], c2_);
                    c3  = fma2(A[i+3], B[i+3], c3);
                }
                u64 sc = add2(add2(c0,c1_), add2(c2_,c3));
                float d0,d1; up2(sc,d0,d1);
                float d = d0+d1;
                float np = nA*nB;
                bool rot = d*d > thr*np;
                big |= (d*d > tiny*np);
                if (__any_sync(FULL, rot)) {
                    float c = 1.0f, s = 0.0f;
                    if (rot) rot_cs(nA, nB, d, c, s);
                    u64 cp = pk2(c,c), sp = pk2(s,s), np2 = pk2(-s,-s);
#pragma unroll
                    for (int i = 0; i < 32; ++i) {
                        u64 x = A[i], y = B[i];
                        A[i] = fma2(sp, x, mul2(cp, y));   // v -> pos 2l (swap)
                        B[i] = fma2(cp, x, mul2(np2, y));  // u -> pos 2l+1
                    }
                    float cc=c*c, ss=s*s, cs2=2.0f*c*s;
                    float nu = cc*nA - cs2*d + ss*nB;
                    float nv = ss*nA + cs2*d + cc*nB;
                    nA = nv; nB = nu;
                } else {
#pragma unroll
                    for (int i = 0; i < 32; ++i) { u64 t=A[i]; A[i]=B[i]; B[i]=t; }
                    float t = nA; nA = nB; nB = t;
                }
            }
            // ---- odd round: pair (B_l, A_{l+1}); positions 0 and 63 idle ----
            {
                float ny = __shfl_down_sync(FULL, nA, 1);
                u64 c0=0ull,c1_=0ull,c2_=0ull,c3=0ull;
#pragma unroll
                for (int i = 0; i < 32; i += 4) {
                    u64 y0 = __shfl_down_sync(FULL, A[i],   1);
                    u64 y1 = __shfl_down_sync(FULL, A[i+1], 1);
                    u64 y2 = __shfl_down_sync(FULL, A[i+2], 1);
                    u64 y3 = __shfl_down_sync(FULL, A[i+3], 1);
                    c0  = fma2(B[i],   y0, c0);
                    c1_ = fma2(B[i+1], y1, c1_);
                    c2_ = fma2(B[i+2], y2, c2_);
                    c3  = fma2(B[i+3], y3, c3);
                }
                u64 sc = add2(add2(c0,c1_), add2(c2_,c3));
                float d0,d1; up2(sc,d0,d1);
                float d = d0+d1;
                float np = nB*ny;
                bool rot = (lane < 31) && (d*d > thr*np);
                big |= (int)((lane < 31) && (d*d > tiny*np));
                if (__any_sync(FULL, rot)) {
                    float c = 1.0f, s = 0.0f;
                    if (rot) rot_cs(nB, ny, d, c, s);
                    u64 cp = pk2(c,c), sp = pk2(s,s), np2 = pk2(-s,-s);
#pragma unroll
                    for (int i = 0; i < 32; ++i) {
                        u64 x = B[i];
                        u64 y = __shfl_down_sync(FULL, A[i], 1);
                        u64 u = fma2(cp, x, mul2(np2, y));
                        u64 v = fma2(sp, x, mul2(cp, y));
                        u64 us = __shfl_up_sync(FULL, u, 1);
                        B[i] = (lane==31) ? B[i] : v;
                        A[i] = (lane==0)  ? A[i] : us;
                    }
                    float cc=c*c, ss=s*s, cs2=2.0f*c*s;
                    float nu = cc*nB - cs2*d + ss*ny;
                    float nv = ss*nB + cs2*d + cc*ny;
                    float nus = __shfl_up_sync(FULL, nu, 1);
                    nB = (lane==31) ? nB : nv;
                    nA = (lane==0)  ? nA : nus;
                } else {
                    // quiet fast-path: pure positional swap across lane boundary
#pragma unroll
                    for (int i = 0; i < 32; ++i) {
                        u64 y  = __shfl_down_sync(FULL, A[i], 1);
                        u64 xs = __shfl_up_sync(FULL, B[i], 1);
                        B[i] = (lane==31) ? B[i] : y;
                        A[i] = (lane==0)  ? A[i] : xs;
                    }
                    float nus = __shfl_up_sync(FULL, nB, 1);
                    nB = (lane==31) ? nB : ny;
                    nA = (lane==0)  ? nA : nus;
                }
            }
        }
        if (!__any_sync(FULL, big)) break;
    }
}

// ----------------------------------------------------------------------------
// Packed warp-GEMM: A2/B2 = columns (2*lane, 2*lane+1) of P = Bcast * Col.
// Bc[k*LD + i] == Bcast[i][k]; broadcast loads are 16B ulonglong2.
// ----------------------------------------------------------------------------
__device__ __forceinline__ void wgemm_p(u64 (&A2)[32], u64 (&B2)[32],
                                        const float* Bc, const float* Csrc, int lane) {
#pragma unroll
    for (int i = 0; i < 32; ++i) { A2[i] = 0ull; B2[i] = 0ull; }
    for (int k = 0; k < 64; ++k) {
        float2 mv = *(const float2*)&Csrc[k*LD + 2*lane];
        u64 m1 = pk2(mv.x, mv.x), m2 = pk2(mv.y, mv.y);
        const ulonglong2* row = (const ulonglong2*)&Bc[k*LD];
#pragma unroll
        for (int j = 0; j < 16; ++j) {
            ulonglong2 xv = row[j];
            A2[2*j]   = fma2(xv.x, m1, A2[2*j]);
            A2[2*j+1] = fma2(xv.y, m1, A2[2*j+1]);
            B2[2*j]   = fma2(xv.x, m2, B2[2*j]);
            B2[2*j+1] = fma2(xv.y, m2, B2[2*j+1]);
        }
    }
}
// Col operand from GLOBAL row-major [k][c] (stride 64)
__device__ __forceinline__ void wgemm_pg(u64 (&A2)[32], u64 (&B2)[32],
                                         const float* Bc, const float* __restrict__ Cg,
                                         int lane) {
#pragma unroll
    for (int i = 0; i < 32; ++i) { A2[i] = 0ull; B2[i] = 0ull; }
    for (int k = 0; k < 64; ++k) {
        float2 mv = *(const float2*)&Cg[k*64 + 2*lane];
        u64 m1 = pk2(mv.x, mv.x), m2 = pk2(mv.y, mv.y);
        const ulonglong2* row = (const ulonglong2*)&Bc[k*LD];
#pragma unroll
        for (int j = 0; j < 16; ++j) {
            ulonglong2 xv = row[j];
            A2[2*j]   = fma2(xv.x, m1, A2[2*j]);
            A2[2*j+1] = fma2(xv.y, m1, A2[2*j+1]);
            B2[2*j]   = fma2(xv.x, m2, B2[2*j]);
            B2[2*j+1] = fma2(xv.y, m2, B2[2*j+1]);
        }
    }
}
// Packed W diag(g) W^T: Wt[k*LD+i] = W[i][k]; g in shared [64]
__device__ __forceinline__ void wouter_p(u64 (&A2)[32], u64 (&B2)[32],
                                         const float* Wt, const float* g, int lane) {
#pragma unroll
    for (int i = 0; i < 32; ++i) { A2[i] = 0ull; B2[i] = 0ull; }
    for (int k = 0; k < 64; ++k) {
        float2 wv = *(const float2*)&Wt[k*LD + 2*lane];
        float gk = g[k];
        float s1 = gk * wv.x, s2 = gk * wv.y;
        u64 m1 = pk2(s1, s1), m2 = pk2(s2, s2);
        const ulonglong2* row = (const ulonglong2*)&Wt[k*LD];
#pragma unroll
        for (int j = 0; j < 16; ++j) {
            ulonglong2 xv = row[j];
            A2[2*j]   = fma2(xv.x, m1, A2[2*j]);
            A2[2*j+1] = fma2(xv.y, m1, A2[2*j+1]);
            B2[2*j]   = fma2(xv.x, m2, B2[2*j]);
            B2[2*j+1] = fma2(xv.y, m2, B2[2*j+1]);
        }
    }
}

// pack columns (2*lane, 2*lane+1) from row-major LD-padded shared
__device__ __forceinline__ void pack_cols(u64 (&A)[32], u64 (&B)[32],
                                          const float* S, int lane) {
#pragma unroll
    for (int i = 0; i < 32; ++i) {
        A[i] = pk2(S[(2*i)*LD + 2*lane],     S[(2*i+1)*LD + 2*lane]);
        B[i] = pk2(S[(2*i)*LD + 2*lane + 1], S[(2*i+1)*LD + 2*lane + 1]);
    }
}
__device__ __forceinline__ void norms_p(const u64 (&A)[32], const u64 (&B)[32],
                                        float& n1, float& n2) {
    u64 a0=0ull,a1=0ull,a2=0ull,a3=0ull, b0=0ull,b1=0ull,b2=0ull,b3=0ull;
#pragma unroll
    for (int i = 0; i < 32; i += 4) {
        a0 = fma2(A[i],   A[i],   a0);
        a1 = fma2(A[i+1], A[i+1], a1);
        a2 = fma2(A[i+2], A[i+2], a2);
        a3 = fma2(A[i+3], A[i+3], a3);
        b0 = fma2(B[i],   B[i],   b0);
        b1 = fma2(B[i+1], B[i+1], b1);
        b2 = fma2(B[i+2], B[i+2], b2);
        b3 = fma2(B[i+3], B[i+3], b3);
    }
    u64 sa = add2(add2(a0,a1), add2(a2,a3));
    u64 sb = add2(add2(b0,b1), add2(b2,b3));
    float x0,x1,y0,y1; up2(sa,x0,x1); up2(sb,y0,y1);
    n1 = fmaxf(x0+x1, 1e-30f);
    n2 = fmaxf(y0+y1, 1e-30f);
}
// write held columns as ROWS 2*lane, 2*lane+1 (u64 stores)
__device__ __forceinline__ void unpack_rows(const u64 (&A)[32], const u64 (&B)[32],
                                            float* S, int lane) {
    u64* r0 = (u64*)&S[(2*lane)*LD];
    u64* r1 = (u64*)&S[(2*lane+1)*LD];
#pragma unroll
    for (int i = 0; i < 32; ++i) {
        r0[i] = A[i];
        r1[i] = B[i];
    }
}
// write held columns as [k][c] scalars (for GEMM column-operand handoff)
__device__ __forceinline__ void unpack_cols(const u64 (&A)[32], const u64 (&B)[32],
                                            float* S, int lane) {
#pragma unroll
    for (int i = 0; i < 32; ++i) {
        float x0,x1,y0,y1;
        up2(A[i],x0,x1); up2(B[i],y0,y1);
        S[(2*i)*LD   + 2*lane]     = x0;
        S[(2*i+1)*LD + 2*lane]     = x1;
        S[(2*i)*LD   + 2*lane + 1] = y0;
        S[(2*i+1)*LD + 2*lane + 1] = y1;
    }
}
// straight copy global NxN row-major -> LD-padded shared (float4)
__device__ __forceinline__ void ld_tile_warp(float* S, const float* __restrict__ G, int lane) {
    const float4* G4 = (const float4*)G;
    for (int idx = lane; idx < 1024; idx += 32) {
        int r = idx >> 4, c = (idx & 15) << 2;
        *(float4*)&S[r*LD + c] = G4[idx];
    }
}
// store held symmetric result columns as rows to global (float4)
__device__ __forceinline__ void st_sym_global(const u64 (&A2)[32], const u64 (&B2)[32],
                                              float* __restrict__ G, int lane) {
#pragma unroll
    for (int j = 0; j < 16; ++j) {
        float x0,x1,y0,y1,z0,z1,w0,w1;
        up2(A2[2*j],x0,x1); up2(A2[2*j+1],y0,y1);
        up2(B2[2*j],z0,z1); up2(B2[2*j+1],w0,w1);
        ((float4*)G)[(2*lane)*16 + j]   = make_float4(x0,x1,y0,y1);
        ((float4*)G)[(2*lane+1)*16 + j] = make_float4(z0,z1,w0,w1);
    }
}

// ----------------------------------------------------------------------------
// Reductions
// ----------------------------------------------------------------------------
__global__ void __launch_bounds__(NT) reduce32_kernel(const float* __restrict__ src,
                                                      float* __restrict__ dst, int Bsz) {
    int j = blockIdx.x;
    int b0 = j * 32;
    int cnt = min(32, Bsz - b0);
    for (int i = threadIdx.x; i < N*N; i += NT) {
        float a = 0.0f;
        for (int k = 0; k < cnt; ++k)
            a += src[(size_t)(b0 + k) * (N*N) + i];
        dst[(size_t)j * (N*N) + i] = a;
    }
}
__global__ void __launch_bounds__(NT) reduceFinal_kernel(const float* __restrict__ part,
                                                         float* __restrict__ dst,
                                                         int nb, float scale) {
    int i = blockIdx.x * NT + threadIdx.x;
    float a = 0.0f;
    for (int j = 0; j < nb; ++j)
        a += part[(size_t)j * (N*N) + i];
    dst[i] = a * scale;
}

// ----------------------------------------------------------------------------
// Single-matrix warp kernels (1 warp)
// ----------------------------------------------------------------------------

// eig(M) -> g_Ms, g_Mis, V -> g_VM.  Warm from g_VM.
__global__ void __launch_bounds__(32) prep_M_kernel(int warm) {
    __shared__ __align__(16) float t0[TILE], t1[TILE];
    __shared__ float sG[64];
    const int lane = threadIdx.x;
    u64 A2[32], B2[32];

    ld_tile_warp(t0, g_M, lane);
    __syncwarp();
    if (warm) {
        ld_tile_warp(t1, g_VM, lane);       // Vp row-major [k][c]
        __syncwarp();
        wgemm_p(A2, B2, t0, t1, lane);      // W0 = M * Vp
    } else {
        pack_cols(A2, B2, t0, lane);
    }

    hestenes_p(A2, B2, lane, 24, 1e-10f, 1e-9f);

    float n1, n2;
    norms_p(A2, B2, n1, n2);
    float inv1 = rsqrtf(n1), inv2 = rsqrtf(n2);
    __syncwarp();
    unpack_rows(A2, B2, t1, lane);          // t1[k][i] = W[i][k]
    sG[2*lane]   = __expf(-0.75f * __logf(n1));   // lambda^{-3/2}
    sG[2*lane+1] = __expf(-0.75f * __logf(n2));
    __syncwarp();

    for (int k = 0; k < 64; ++k) {          // V -> g_VM row-major [k][c]
        g_VM[k*64 + 2*lane]     = t1[(2*lane)*LD + k]   * inv1;
        g_VM[k*64 + 2*lane + 1] = t1[(2*lane+1)*LD + k] * inv2;
    }
    wouter_p(A2, B2, t1, sG, lane);         // Ms
    st_sym_global(A2, B2, g_Ms, lane);
    sG[2*lane]   = __expf(-1.25f * __logf(n1));   // lambda^{-5/2} -> Mis
    sG[2*lane+1] = __expf(-1.25f * __logf(n2));
    __syncwarp();
    wouter_p(A2, B2, t1, sG, lane);
    st_sym_global(A2, B2, g_Mis, lane);
}

// M <- sym(Ms expm(L) Ms).  eig(L + sigma I) warm from g_VL.
__global__ void __launch_bounds__(32) update_M_kernel(int warm) {
    __shared__ __align__(16) float t0[TILE], t1[TILE];
    __shared__ float sG[64];
    __shared__ float s_sigma;
    const int lane = threadIdx.x;
    const unsigned FULL = 0xffffffffu;
    u64 A2[32], B2[32];

    float fro2 = 0.0f;
    for (int idx = lane; idx < N*N; idx += 32) {
        float v = g_L[idx];
        t0[(idx>>6)*LD + (idx&63)] = v;
        fro2 = fmaf(v, v, fro2);
    }
#pragma unroll
    for (int o = 16; o > 0; o >>= 1) fro2 += __shfl_down_sync(FULL, fro2, o);
    if (lane == 0) s_sigma = 1.05f * sqrtf(fro2) + 1e-12f;
    __syncwarp();
    const float sigma = s_sigma;

    if (warm) {
        ld_tile_warp(t1, g_VL, lane);
        __syncwarp();
        wgemm_p(A2, B2, t0, t1, lane);      // L*Vp
        u64 sg = pk2(sigma, sigma);
#pragma unroll
        for (int i = 0; i < 32; ++i) {      // + sigma*Vp
            A2[i] = fma2(sg, pk2(t1[(2*i)*LD + 2*lane],   t1[(2*i+1)*LD + 2*lane]),   A2[i]);
            B2[i] = fma2(sg, pk2(t1[(2*i)*LD + 2*lane+1], t1[(2*i+1)*LD + 2*lane+1]), B2[i]);
        }
    } else {
#pragma unroll
        for (int i = 0; i < 32; ++i) {
            float a0 = t0[(2*i)*LD + 2*lane]     + ((i == lane) ? sigma : 0.0f);
            float a1 = t0[(2*i+1)*LD + 2*lane];
            float b0 = t0[(2*i)*LD + 2*lane + 1];
            float b1 = t0[(2*i+1)*LD + 2*lane+1] + ((i == lane) ? sigma : 0.0f);
            A2[i] = pk2(a0, a1);
            B2[i] = pk2(b0, b1);
        }
    }

    hestenes_p(A2, B2, lane, 24, 1e-10f, 1e-9f);

    float n1, n2;
    norms_p(A2, B2, n1, n2);
    float inv1 = rsqrtf(n1), inv2 = rsqrtf(n2);
    __syncwarp();
    unpack_rows(A2, B2, t0, lane);          // t0 = W^T
    sG[2*lane]   = __expf(__fsqrt_rn(n1) - sigma) * __fdividef(1.0f, n1);
    sG[2*lane+1] = __expf(__fsqrt_rn(n2) - sigma) * __fdividef(1.0f, n2);
    __syncwarp();
    for (int k = 0; k < 64; ++k) {          // V -> g_VL
        g_VL[k*64 + 2*lane]     = t0[(2*lane)*LD + k]   * inv1;
        g_VL[k*64 + 2*lane + 1] = t0[(2*lane+1)*LD + k] * inv2;
    }
    wouter_p(A2, B2, t0, sG, lane);         // E = expm(L)
    __syncwarp();
    unpack_rows(A2, B2, t1, lane);          // t1[k][i] = E[i][k] (E symmetric)
    __syncwarp();
    ld_tile_warp(t0, g_Ms, lane);           // t0 = Ms (symmetric)
    __syncwarp();
    wgemm_p(A2, B2, t0, t1, lane);          // T = Ms * E
    __syncwarp();
    unpack_rows(A2, B2, t1, lane);          // t1[k][i] = T[i][k]
    __syncwarp();
    wgemm_p(A2, B2, t1, t0, lane);          // Mn = T * Ms
    __syncwarp();
    unpack_rows(A2, B2, t0, lane);          // t0[c][i] = Mn[i][c]
    __syncwarp();
    for (int idx = lane; idx < N*N; idx += 32) {
        int i = idx >> 6, j = idx & 63;
        g_M[idx] = 0.5f * (t0[j*LD + i] + t0[i*LD + j]);
    }
}

// C = expm(0.25 (bias + bias^T)) * invsqrtm(M);  stores C^T row-major in g_Ct
__global__ void __launch_bounds__(32) final_prep_kernel(const float* __restrict__ bias) {
    __shared__ __align__(16) float t0[TILE], t1[TILE];
    __shared__ float sG[64];
    __shared__ float s_sigma;
    const int lane = threadIdx.x;
    const unsigned FULL = 0xffffffffu;
    u64 A2[32], B2[32];

    // ---- eig(M) warm from g_VM -> Mis rows into t1 ----
    ld_tile_warp(t0, g_M, lane);
    ld_tile_warp(t1, g_VM, lane);
    __syncwarp();
    wgemm_p(A2, B2, t0, t1, lane);          // W0 = M * Vp
    hestenes_p(A2, B2, lane, 24, 1e-10f, 1e-9f);
    float n1, n2;
    norms_p(A2, B2, n1, n2);
    __syncwarp();
    unpack_rows(A2, B2, t0, lane);          // t0 = W^T
    sG[2*lane]   = __expf(-1.25f * __logf(n1));
    sG[2*lane+1] = __expf(-1.25f * __logf(n2));
    __syncwarp();
    wouter_p(A2, B2, t0, sG, lane);         // Mis columns
    __syncwarp();
    unpack_rows(A2, B2, t1, lane);          // t1[k][i] = Mis[i][k] (symmetric)
    __syncwarp();

    // ---- eig(0.25(b+b^T) + sigma I) -> Bs ----
    float fro2 = 0.0f;
    for (int idx = lane; idx < N*N; idx += 32) {
        int i = idx >> 6, j = idx & 63;
        float v = 0.25f * (bias[i*64 + j] + bias[j*64 + i]);
        t0[i*LD + j] = v;
        fro2 = fmaf(v, v, fro2);
    }
#pragma unroll
    for (int o = 16; o > 0; o >>= 1) fro2 += __shfl_down_sync(FULL, fro2, o);
    if (lane == 0) s_sigma = 1.05f * sqrtf(fro2) + 1e-12f;
    __syncwarp();
    const float sb = s_sigma;
#pragma unroll
    for (int i = 0; i < 32; ++i) {
        float a0 = t0[(2*i)*LD + 2*lane]     + ((i == lane) ? sb : 0.0f);
        float a1 = t0[(2*i+1)*LD + 2*lane];
        float b0 = t0[(2*i)*LD + 2*lane + 1];
        float b1 = t0[(2*i+1)*LD + 2*lane+1] + ((i == lane) ? sb : 0.0f);
        A2[i] = pk2(a0, a1);
        B2[i] = pk2(b0, b1);
    }
    hestenes_p(A2, B2, lane, 24, 1e-10f, 1e-9f);
    norms_p(A2, B2, n1, n2);
    __syncwarp();
    unpack_rows(A2, B2, t0, lane);          // t0 = Wb^T
    sG[2*lane]   = __expf(__fsqrt_rn(n1) - sb) * __fdividef(1.0f, n1);
    sG[2*lane+1] = __expf(__fsqrt_rn(n2) - sb) * __fdividef(1.0f, n2);
    __syncwarp();
    wouter_p(A2, B2, t0, sG, lane);         // Bs columns
    __syncwarp();
    unpack_rows(A2, B2, t0, lane);          // t0[k][i] = Bs[i][k] (symmetric)
    __syncwarp();
    wgemm_p(A2, B2, t0, t1, lane);          // C = Bs * Mis (cols 2lane, 2lane+1)
    // store C^T row-major: g_Ct[c*64 + j] = C[j][c]
    {
        u64* r0 = (u64*)&g_Ct[(2*lane)*64];
        u64* r1 = (u64*)&g_Ct[(2*lane+1)*64];
#pragma unroll
        for (int i = 0; i < 32; ++i) { r0[i] = A2[i]; r1[i] = B2[i]; }
    }
}

// ----------------------------------------------------------------------------
// Batch logm: one warp per matrix, WPB (=9) per block; 288 threads keeps the
// natural ~212 regs/thread spill-free while adding a 9th warp per SM.
// ----------------------------------------------------------------------------
__global__ void __launch_bounds__(NTB, 1) batch_log_kernel(const float* __restrict__ data,
                                                           int warm, int store_v, int Bsz) {
    extern __shared__ __align__(16) float sm[];
    float* mis = sm;                          // 64 x LD, shared by all warps
    const int tid  = threadIdx.x;
    const int wid  = tid >> 5;
    const int lane = tid & 31;
    float* tile = sm + TILE * (1 + wid);
    float* sGw  = sm + (1 + WPB)*TILE + wid*64;

    {
        const float4* G4 = (const float4*)g_Mis;
        for (int idx = tid; idx < 1024; idx += NTB) {
            int r = idx >> 4, c = (idx & 15) << 2;
            *(float4*)&mis[r*LD + c] = G4[idx];
        }
    }
    __syncthreads();

    const int b = blockIdx.x * WPB + wid;
    if (b >= Bsz) return;

    ld_tile_warp(tile, data + (size_t)b * (N*N), lane);   // X (symmetric)
    __syncwarp();

    u64 A2[32], B2[32];

    wgemm_p(A2, B2, tile, mis, lane);        // Z = X * Mis
    __syncwarp();
    unpack_cols(A2, B2, tile, lane);         // Z as [k][c]
    __syncwarp();
    wgemm_p(A2, B2, mis, tile, lane);        // Y = Mis * Z

    if (warm) {
        __syncwarp();
        unpack_rows(A2, B2, tile, lane);     // tile[k][i] = Y[i][k] (Y symmetric)
        __syncwarp();
        wgemm_pg(A2, B2, tile, g_Vw + (size_t)b * (N*N), lane);   // W0 = Y * Vp
    }

    hestenes_p(A2, B2, lane, 16, 1e-8f, 1e-5f);

    float n1, n2;
    norms_p(A2, B2, n1, n2);
    float inv1 = rsqrtf(n1), inv2 = rsqrtf(n2);
    __syncwarp();
    unpack_rows(A2, B2, tile, lane);         // tile = W^T
    sGw[2*lane]   = __fdividef(0.5f * __logf(n1), n1);   // log(l)/l^2
    sGw[2*lane+1] = __fdividef(0.5f * __logf(n2), n2);
    __syncwarp();

    wouter_p(A2, B2, tile, sGw, lane);       // O = W diag(g) W^T
    st_sym_global(A2, B2, g_scratch + (size_t)b * (N*N), lane);

    if (store_v) {
        float* Vd = g_Vw + (size_t)b * (N*N);
#pragma unroll
        for (int k = 0; k < 64; ++k) {
            Vd[k*64 + 2*lane]     = tile[(2*lane)*LD + k]   * inv1;
            Vd[k*64 + 2*lane + 1] = tile[(2*lane+1)*LD + k] * inv2;
        }
    }
}

// ----------------------------------------------------------------------------
// Apply: out_b = C X_b C^T (symmetric). One warp per matrix, WPB per block.
// ----------------------------------------------------------------------------
__global__ void __launch_bounds__(NTB, 1) apply_kernel(const float* __restrict__ data,
                                                       float* __restrict__ out, int Bsz) {
    extern __shared__ __align__(16) float sm[];
    float* ct = sm;                           // 64 x LD, shared by all warps
    const int tid  = threadIdx.x;
    const int wid  = tid >> 5;
    const int lane = tid & 31;
    float* tile = sm + TILE * (1 + wid);

    {
        const float4* G4 = (const float4*)g_Ct;
        for (int idx = tid; idx < 1024; idx += NTB) {
            int r = idx >> 4, c = (idx & 15) << 2;
            *(float4*)&ct[r*LD + c] = G4[idx];
        }
    }
    __syncthreads();

    const int b = blockIdx.x * WPB + wid;
    if (b >= Bsz) return;

    ld_tile_warp(tile, data + (size_t)b * (N*N), lane);
    __syncwarp();

    u64 A2[32], B2[32];
    wgemm_p(A2, B2, tile, ct, lane);         // Z = X * C^T (cols 2lane, 2lane+1)
    __syncwarp();
    unpack_cols(A2, B2, tile, lane);         // Z as [k][c]
    __syncwarp();
    wgemm_p(A2, B2, ct, tile, lane);         // out = C * Z (symmetric)
    st_sym_global(A2, B2, out + (size_t)b * (N*N), lane);
}

// ----------------------------------------------------------------------------
// Host launcher (graph-capturable)
// ----------------------------------------------------------------------------
extern "C" void kernel_launch(void* const* d_in, const int* in_sizes, int n_in,
                              void* d_out, int out_size) {
    const float* data = (const float*)d_in[0];
    const float* bias = (const float*)d_in[1];
    int sz0 = in_sizes[0], sz1 = (n_in > 1) ? in_sizes[1] : 0;
    if (sz0 == N*N && sz1 > N*N) {
        data = (const float*)d_in[1];
        bias = (const float*)d_in[0];
        int t = sz0; sz0 = sz1; sz1 = t;
    }
    int Bsz = sz0 / (N*N);
    if (Bsz > MAXB) Bsz = MAXB;
    float* out = (float*)d_out;

    const size_t shmemB = ((1 + WPB) * TILE + WPB * 64) * sizeof(float);  // 176,384 B
    cudaFuncSetAttribute(batch_log_kernel, cudaFuncAttributeMaxDynamicSharedMemorySize, (int)shmemB);
    cudaFuncSetAttribute(apply_kernel,     cudaFuncAttributeMaxDynamicSharedMemorySize, (int)shmemB);

    float *pM, *pL, *pScr, *pPart;
    cudaGetSymbolAddress((void**)&pM,    g_M);
    cudaGetSymbolAddress((void**)&pL,    g_L);
    cudaGetSymbolAddress((void**)&pScr,  g_scratch);
    cudaGetSymbolAddress((void**)&pPart, g_partial);

    const int nb1 = (Bsz + 31) / 32;
    const int nbW = (Bsz + WPB - 1) / WPB;
    const float inv = 1.0f / (float)Bsz;

    reduce32_kernel    <<<nb1, NT>>>(data, pPart, Bsz);
    reduceFinal_kernel <<<16,  NT>>>(pPart, pM, nb1, inv);

    for (int it = 0; it < 5; ++it) {
        prep_M_kernel    <<<1,   32>>>(it > 0 ? 1 : 0);
        batch_log_kernel <<<nbW, NTB, shmemB>>>(data, it > 0 ? 1 : 0, it < 4 ? 1 : 0, Bsz);
        reduce32_kernel    <<<nb1, NT>>>(pScr, pPart, Bsz);
        reduceFinal_kernel <<<16,  NT>>>(pPart, pL, nb1, inv);
        update_M_kernel  <<<1,   32>>>(it > 0 ? 1 : 0);
    }

    final_prep_kernel <<<1,   32>>>(bias);
    apply_kernel      <<<nbW, NTB, shmemB>>>(data, out, Bsz);
}

// round 16
// speedup vs baseline: 1.2170x; 1.2170x over previous
#include <cuda_runtime.h>
#include <math.h>

#define N    64
#define LD   68            // padded leading dim (floats); 16B-aligned rows
#define NT   256
#define TILE (N*LD)        // 4352 floats
#define MAXB 8192

typedef unsigned long long u64;

// ----------------------------------------------------------------------------
// f32x2 packed helpers (sm_103a packed FP32 pipe; only reachable via PTX)
// ----------------------------------------------------------------------------
__device__ __forceinline__ u64 pk2(float lo, float hi) {
    u64 r; asm("mov.b64 %0,{%1,%2};" : "=l"(r) : "f"(lo), "f"(hi)); return r;
}
__device__ __forceinline__ void up2(u64 v, float& lo, float& hi) {
    asm("mov.b64 {%0,%1},%2;" : "=f"(lo), "=f"(hi) : "l"(v));
}
__device__ __forceinline__ u64 fma2(u64 a, u64 b, u64 c) {
    u64 r; asm("fma.rn.f32x2 %0,%1,%2,%3;" : "=l"(r) : "l"(a), "l"(b), "l"(c)); return r;
}
__device__ __forceinline__ u64 mul2(u64 a, u64 b) {
    u64 r; asm("mul.rn.f32x2 %0,%1,%2;" : "=l"(r) : "l"(a), "l"(b)); return r;
}
__device__ __forceinline__ u64 add2(u64 a, u64 b) {
    u64 r; asm("add.rn.f32x2 %0,%1,%2;" : "=l"(r) : "l"(a), "l"(b)); return r;
}

// Fast rotation scalars (MUFU approx; Jacobi self-corrects ulp-level errors)
__device__ __forceinline__ void rot_cs(float na, float nb, float d,
                                       float& c, float& s) {
    float ta = __fdividef(nb - na, 2.0f * d);
    float h  = fmaf(ta, ta, 1.0f);
    float t  = copysignf(1.0f, ta) * __fdividef(1.0f, fabsf(ta) + h * rsqrtf(h));
    c = rsqrtf(fmaf(t, t, 1.0f));
    s = t * c;
}

// ----------------------------------------------------------------------------
// Global scratch
// ----------------------------------------------------------------------------
__device__ float g_M  [N*N];
__device__ float g_Ms [N*N];
__device__ float g_Mis[N*N];
__device__ float g_L  [N*N];
__device__ float g_Ct [N*N];                   // C^T row-major (= C columns as rows)
__device__ float g_VM [N*N];                   // warm-start eigvecs of M (row-major [k][c])
__device__ float g_VL [N*N];                   // warm-start eigvecs of L+sI
__device__ float g_scratch[(size_t)MAXB*N*N];  // per-matrix logm
__device__ float g_Vw     [(size_t)MAXB*N*N];  // per-matrix eigvecs, row-major [k][c]
__device__ float g_partial[(MAXB/32)*N*N];

// ----------------------------------------------------------------------------
// Packed one-sided (Hestenes) Jacobi, odd-even ordering. Lane l holds columns
// at positions 2l (A) and 2l+1 (B); each column = 32 packed f32x2 values.
// Sweep exit: when a full sweep saw NO pair with d^2 > tiny*nA*nB.
// ----------------------------------------------------------------------------
__device__ __forceinline__ void hestenes_p(u64 (&A)[32], u64 (&B)[32],
                                           int lane, int max_sweeps,
                                           float thr, float tiny) {
    const unsigned FULL = 0xffffffffu;
    for (int sweep = 0; sweep < max_sweeps; ++sweep) {
        float nA, nB;
        {
            u64 a0=0ull,a1=0ull,a2=0ull,a3=0ull, b0=0ull,b1=0ull,b2=0ull,b3=0ull;
#pragma unroll
            for (int i = 0; i < 32; i += 4) {
                a0 = fma2(A[i],   A[i],   a0);
                a1 = fma2(A[i+1], A[i+1], a1);
                a2 = fma2(A[i+2], A[i+2], a2);
                a3 = fma2(A[i+3], A[i+3], a3);
                b0 = fma2(B[i],   B[i],   b0);
                b1 = fma2(B[i+1], B[i+1], b1);
                b2 = fma2(B[i+2], B[i+2], b2);
                b3 = fma2(B[i+3], B[i+3], b3);
            }
            u64 sa = add2(add2(a0,a1), add2(a2,a3));
            u64 sb = add2(add2(b0,b1), add2(b2,b3));
            float x0,x1,y0,y1; up2(sa,x0,x1); up2(sb,y0,y1);
            nA = x0+x1; nB = y0+y1;
        }
        int big = 0;   // per-lane: saw any pair above the tiny threshold
        for (int rr = 0; rr < 32; ++rr) {
            // ---- even round: pair (A,B) within lane ----
            {
                u64 c0=0ull,c1_=0ull,c2_=0ull,c3=0ull;
#pragma unroll
                for (int i = 0; i < 32; i += 4) {
                    c0  = fma2(A[i],   B[i],   c0);
                    c1_ = fma2(A[i+1], B[i+1], c1_);
                    c2_ = fma2(A[i+2], B[i+2], c2_);
                    c3  = fma2(A[i+3], B[i+3], c3);
                }
                u64 sc = add2(add2(c0,c1_), add2(c2_,c3));
                float d0,d1; up2(sc,d0,d1);
                float d = d0+d1;
                float np = nA*nB;
                bool rot = d*d > thr*np;
                big |= (d*d > tiny*np);
                if (__any_sync(FULL, rot)) {
                    float c = 1.0f, s = 0.0f;
                    if (rot) rot_cs(nA, nB, d, c, s);
                    u64 cp = pk2(c,c), sp = pk2(s,s), np2 = pk2(-s,-s);
#pragma unroll
                    for (int i = 0; i < 32; ++i) {
                        u64 x = A[i], y = B[i];
                        A[i] = fma2(sp, x, mul2(cp, y));   // v -> pos 2l (swap)
                        B[i] = fma2(cp, x, mul2(np2, y));  // u -> pos 2l+1
                    }
                    float cc=c*c, ss=s*s, cs2=2.0f*c*s;
                    float nu = cc*nA - cs2*d + ss*nB;
                    float nv = ss*nA + cs2*d + cc*nB;
                    nA = nv; nB = nu;
                } else {
#pragma unroll
                    for (int i = 0; i < 32; ++i) { u64 t=A[i]; A[i]=B[i]; B[i]=t; }
                    float t = nA; nA = nB; nB = t;
                }
            }
            // ---- odd round: pair (B_l, A_{l+1}); positions 0 and 63 idle ----
            {
                float ny = __shfl_down_sync(FULL, nA, 1);
                u64 c0=0ull,c1_=0ull,c2_=0ull,c3=0ull;
#pragma unroll
                for (int i = 0; i < 32; i += 4) {
                    u64 y0 = __shfl_down_sync(FULL, A[i],   1);
                    u64 y1 = __shfl_down_sync(FULL, A[i+1], 1);
                    u64 y2 = __shfl_down_sync(FULL, A[i+2], 1);
                    u64 y3 = __shfl_down_sync(FULL, A[i+3], 1);
                    c0  = fma2(B[i],   y0, c0);
                    c1_ = fma2(B[i+1], y1, c1_);
                    c2_ = fma2(B[i+2], y2, c2_);
                    c3  = fma2(B[i+3], y3, c3);
                }
                u64 sc = add2(add2(c0,c1_), add2(c2_,c3));
                float d0,d1; up2(sc,d0,d1);
                float d = d0+d1;
                float np = nB*ny;
                bool rot = (lane < 31) && (d*d > thr*np);
                big |= (int)((lane < 31) && (d*d > tiny*np));
                if (__any_sync(FULL, rot)) {
                    float c = 1.0f, s = 0.0f;
                    if (rot) rot_cs(nB, ny, d, c, s);
                    u64 cp = pk2(c,c), sp = pk2(s,s), np2 = pk2(-s,-s);
#pragma unroll
                    for (int i = 0; i < 32; ++i) {
                        u64 x = B[i];
                        u64 y = __shfl_down_sync(FULL, A[i], 1);
                        u64 u = fma2(cp, x, mul2(np2, y));
                        u64 v = fma2(sp, x, mul2(cp, y));
                        u64 us = __shfl_up_sync(FULL, u, 1);
                        B[i] = (lane==31) ? B[i] : v;
                        A[i] = (lane==0)  ? A[i] : us;
                    }
                    float cc=c*c, ss=s*s, cs2=2.0f*c*s;
                    float nu = cc*nB - cs2*d + ss*ny;
                    float nv = ss*nB + cs2*d + cc*ny;
                    float nus = __shfl_up_sync(FULL, nu, 1);
                    nB = (lane==31) ? nB : nv;
                    nA = (lane==0)  ? nA : nus;
                } else {
                    // quiet fast-path: pure positional swap across lane boundary
#pragma unroll
                    for (int i = 0; i < 32; ++i) {
                        u64 y  = __shfl_down_sync(FULL, A[i], 1);
                        u64 xs = __shfl_up_sync(FULL, B[i], 1);
                        B[i] = (lane==31) ? B[i] : y;
                        A[i] = (lane==0)  ? A[i] : xs;
                    }
                    float nus = __shfl_up_sync(FULL, nB, 1);
                    nB = (lane==31) ? nB : ny;
                    nA = (lane==0)  ? nA : nus;
                }
            }
        }
        if (!__any_sync(FULL, big)) break;
    }
}

// ----------------------------------------------------------------------------
// Packed warp-GEMM: A2/B2 = columns (2*lane, 2*lane+1) of P = Bcast * Col.
// Bc[k*LD + i] == Bcast[i][k]; broadcast loads are 16B ulonglong2.
// ----------------------------------------------------------------------------
__device__ __forceinline__ void wgemm_p(u64 (&A2)[32], u64 (&B2)[32],
                                        const float* Bc, const float* Csrc, int lane) {
#pragma unroll
    for (int i = 0; i < 32; ++i) { A2[i] = 0ull; B2[i] = 0ull; }
    for (int k = 0; k < 64; ++k) {
        float2 mv = *(const float2*)&Csrc[k*LD + 2*lane];
        u64 m1 = pk2(mv.x, mv.x), m2 = pk2(mv.y, mv.y);
        const ulonglong2* row = (const ulonglong2*)&Bc[k*LD];
#pragma unroll
        for (int j = 0; j < 16; ++j) {
            ulonglong2 xv = row[j];
            A2[2*j]   = fma2(xv.x, m1, A2[2*j]);
            A2[2*j+1] = fma2(xv.y, m1, A2[2*j+1]);
            B2[2*j]   = fma2(xv.x, m2, B2[2*j]);
            B2[2*j+1] = fma2(xv.y, m2, B2[2*j+1]);
        }
    }
}
// Col operand from GLOBAL row-major [k][c] (stride 64)
__device__ __forceinline__ void wgemm_pg(u64 (&A2)[32], u64 (&B2)[32],
                                         const float* Bc, const float* __restrict__ Cg,
                                         int lane) {
#pragma unroll
    for (int i = 0; i < 32; ++i) { A2[i] = 0ull; B2[i] = 0ull; }
    for (int k = 0; k < 64; ++k) {
        float2 mv = *(const float2*)&Cg[k*64 + 2*lane];
        u64 m1 = pk2(mv.x, mv.x), m2 = pk2(mv.y, mv.y);
        const ulonglong2* row = (const ulonglong2*)&Bc[k*LD];
#pragma unroll
        for (int j = 0; j < 16; ++j) {
            ulonglong2 xv = row[j];
            A2[2*j]   = fma2(xv.x, m1, A2[2*j]);
            A2[2*j+1] = fma2(xv.y, m1, A2[2*j+1]);
            B2[2*j]   = fma2(xv.x, m2, B2[2*j]);
            B2[2*j+1] = fma2(xv.y, m2, B2[2*j+1]);
        }
    }
}
// Packed W diag(g) W^T: Wt[k*LD+i] = W[i][k]; g in shared [64]
__device__ __forceinline__ void wouter_p(u64 (&A2)[32], u64 (&B2)[32],
                                         const float* Wt, const float* g, int lane) {
#pragma unroll
    for (int i = 0; i < 32; ++i) { A2[i] = 0ull; B2[i] = 0ull; }
    for (int k = 0; k < 64; ++k) {
        float2 wv = *(const float2*)&Wt[k*LD + 2*lane];
        float gk = g[k];
        float s1 = gk * wv.x, s2 = gk * wv.y;
        u64 m1 = pk2(s1, s1), m2 = pk2(s2, s2);
        const ulonglong2* row = (const ulonglong2*)&Wt[k*LD];
#pragma unroll
        for (int j = 0; j < 16; ++j) {
            ulonglong2 xv = row[j];
            A2[2*j]   = fma2(xv.x, m1, A2[2*j]);
            A2[2*j+1] = fma2(xv.y, m1, A2[2*j+1]);
            B2[2*j]   = fma2(xv.x, m2, B2[2*j]);
            B2[2*j+1] = fma2(xv.y, m2, B2[2*j+1]);
        }
    }
}

// pack columns (2*lane, 2*lane+1) from row-major LD-padded shared
__device__ __forceinline__ void pack_cols(u64 (&A)[32], u64 (&B)[32],
                                          const float* S, int lane) {
#pragma unroll
    for (int i = 0; i < 32; ++i) {
        A[i] = pk2(S[(2*i)*LD + 2*lane],     S[(2*i+1)*LD + 2*lane]);
        B[i] = pk2(S[(2*i)*LD + 2*lane + 1], S[(2*i+1)*LD + 2*lane + 1]);
    }
}
__device__ __forceinline__ void norms_p(const u64 (&A)[32], const u64 (&B)[32],
                                        float& n1, float& n2) {
    u64 a0=0ull,a1=0ull,a2=0ull,a3=0ull, b0=0ull,b1=0ull,b2=0ull,b3=0ull;
#pragma unroll
    for (int i = 0; i < 32; i += 4) {
        a0 = fma2(A[i],   A[i],   a0);
        a1 = fma2(A[i+1], A[i+1], a1);
        a2 = fma2(A[i+2], A[i+2], a2);
        a3 = fma2(A[i+3], A[i+3], a3);
        b0 = fma2(B[i],   B[i],   b0);
        b1 = fma2(B[i+1], B[i+1], b1);
        b2 = fma2(B[i+2], B[i+2], b2);
        b3 = fma2(B[i+3], B[i+3], b3);
    }
    u64 sa = add2(add2(a0,a1), add2(a2,a3));
    u64 sb = add2(add2(b0,b1), add2(b2,b3));
    float x0,x1,y0,y1; up2(sa,x0,x1); up2(sb,y0,y1);
    n1 = fmaxf(x0+x1, 1e-30f);
    n2 = fmaxf(y0+y1, 1e-30f);
}
// write held columns as ROWS 2*lane, 2*lane+1 (u64 stores)
__device__ __forceinline__ void unpack_rows(const u64 (&A)[32], const u64 (&B)[32],
                                            float* S, int lane) {
    u64* r0 = (u64*)&S[(2*lane)*LD];
    u64* r1 = (u64*)&S[(2*lane+1)*LD];
#pragma unroll
    for (int i = 0; i < 32; ++i) {
        r0[i] = A[i];
        r1[i] = B[i];
    }
}
// write held columns as [k][c] scalars (for GEMM column-operand handoff)
__device__ __forceinline__ void unpack_cols(const u64 (&A)[32], const u64 (&B)[32],
                                            float* S, int lane) {
#pragma unroll
    for (int i = 0; i < 32; ++i) {
        float x0,x1,y0,y1;
        up2(A[i],x0,x1); up2(B[i],y0,y1);
        S[(2*i)*LD   + 2*lane]     = x0;
        S[(2*i+1)*LD + 2*lane]     = x1;
        S[(2*i)*LD   + 2*lane + 1] = y0;
        S[(2*i+1)*LD + 2*lane + 1] = y1;
    }
}
// straight copy global NxN row-major -> LD-padded shared (float4)
__device__ __forceinline__ void ld_tile_warp(float* S, const float* __restrict__ G, int lane) {
    const float4* G4 = (const float4*)G;
    for (int idx = lane; idx < 1024; idx += 32) {
        int r = idx >> 4, c = (idx & 15) << 2;
        *(float4*)&S[r*LD + c] = G4[idx];
    }
}
// store held symmetric result columns as rows to global (float4)
__device__ __forceinline__ void st_sym_global(const u64 (&A2)[32], const u64 (&B2)[32],
                                              float* __restrict__ G, int lane) {
#pragma unroll
    for (int j = 0; j < 16; ++j) {
        float x0,x1,y0,y1,z0,z1,w0,w1;
        up2(A2[2*j],x0,x1); up2(A2[2*j+1],y0,y1);
        up2(B2[2*j],z0,z1); up2(B2[2*j+1],w0,w1);
        ((float4*)G)[(2*lane)*16 + j]   = make_float4(x0,x1,y0,y1);
        ((float4*)G)[(2*lane+1)*16 + j] = make_float4(z0,z1,w0,w1);
    }
}

// ----------------------------------------------------------------------------
// Reductions
// ----------------------------------------------------------------------------
__global__ void __launch_bounds__(NT) reduce32_kernel(const float* __restrict__ src,
                                                      float* __restrict__ dst, int Bsz) {
    int j = blockIdx.x;
    int b0 = j * 32;
    int cnt = min(32, Bsz - b0);
    for (int i = threadIdx.x; i < N*N; i += NT) {
        float a = 0.0f;
        for (int k = 0; k < cnt; ++k)
            a += src[(size_t)(b0 + k) * (N*N) + i];
        dst[(size_t)j * (N*N) + i] = a;
    }
}
__global__ void __launch_bounds__(NT) reduceFinal_kernel(const float* __restrict__ part,
                                                         float* __restrict__ dst,
                                                         int nb, float scale) {
    int i = blockIdx.x * NT + threadIdx.x;
    float a = 0.0f;
    for (int j = 0; j < nb; ++j)
        a += part[(size_t)j * (N*N) + i];
    dst[i] = a * scale;
}

// ----------------------------------------------------------------------------
// Single-matrix warp kernels (1 warp)
// ----------------------------------------------------------------------------

// eig(M) -> g_Ms, g_Mis, V -> g_VM.  Warm from g_VM.
__global__ void __launch_bounds__(32) prep_M_kernel(int warm) {
    __shared__ __align__(16) float t0[TILE], t1[TILE];
    __shared__ float sG[64];
    const int lane = threadIdx.x;
    u64 A2[32], B2[32];

    ld_tile_warp(t0, g_M, lane);
    __syncwarp();
    if (warm) {
        ld_tile_warp(t1, g_VM, lane);       // Vp row-major [k][c]
        __syncwarp();
        wgemm_p(A2, B2, t0, t1, lane);      // W0 = M * Vp
    } else {
        pack_cols(A2, B2, t0, lane);
    }

    hestenes_p(A2, B2, lane, 24, 1e-10f, 1e-9f);

    float n1, n2;
    norms_p(A2, B2, n1, n2);
    float inv1 = rsqrtf(n1), inv2 = rsqrtf(n2);
    __syncwarp();
    unpack_rows(A2, B2, t1, lane);          // t1[k][i] = W[i][k]
    sG[2*lane]   = __expf(-0.75f * __logf(n1));   // lambda^{-3/2}
    sG[2*lane+1] = __expf(-0.75f * __logf(n2));
    __syncwarp();

    for (int k = 0; k < 64; ++k) {          // V -> g_VM row-major [k][c]
        g_VM[k*64 + 2*lane]     = t1[(2*lane)*LD + k]   * inv1;
        g_VM[k*64 + 2*lane + 1] = t1[(2*lane+1)*LD + k] * inv2;
    }
    wouter_p(A2, B2, t1, sG, lane);         // Ms
    st_sym_global(A2, B2, g_Ms, lane);
    sG[2*lane]   = __expf(-1.25f * __logf(n1));   // lambda^{-5/2} -> Mis
    sG[2*lane+1] = __expf(-1.25f * __logf(n2));
    __syncwarp();
    wouter_p(A2, B2, t1, sG, lane);
    st_sym_global(A2, B2, g_Mis, lane);
}

// M <- sym(Ms expm(L) Ms).  eig(L + sigma I) warm from g_VL.
__global__ void __launch_bounds__(32) update_M_kernel(int warm) {
    __shared__ __align__(16) float t0[TILE], t1[TILE];
    __shared__ float sG[64];
    __shared__ float s_sigma;
    const int lane = threadIdx.x;
    const unsigned FULL = 0xffffffffu;
    u64 A2[32], B2[32];

    float fro2 = 0.0f;
    for (int idx = lane; idx < N*N; idx += 32) {
        float v = g_L[idx];
        t0[(idx>>6)*LD + (idx&63)] = v;
        fro2 = fmaf(v, v, fro2);
    }
#pragma unroll
    for (int o = 16; o > 0; o >>= 1) fro2 += __shfl_down_sync(FULL, fro2, o);
    if (lane == 0) s_sigma = 1.05f * sqrtf(fro2) + 1e-12f;
    __syncwarp();
    const float sigma = s_sigma;

    if (warm) {
        ld_tile_warp(t1, g_VL, lane);
        __syncwarp();
        wgemm_p(A2, B2, t0, t1, lane);      // L*Vp
        u64 sg = pk2(sigma, sigma);
#pragma unroll
        for (int i = 0; i < 32; ++i) {      // + sigma*Vp
            A2[i] = fma2(sg, pk2(t1[(2*i)*LD + 2*lane],   t1[(2*i+1)*LD + 2*lane]),   A2[i]);
            B2[i] = fma2(sg, pk2(t1[(2*i)*LD + 2*lane+1], t1[(2*i+1)*LD + 2*lane+1]), B2[i]);
        }
    } else {
#pragma unroll
        for (int i = 0; i < 32; ++i) {
            float a0 = t0[(2*i)*LD + 2*lane]     + ((i == lane) ? sigma : 0.0f);
            float a1 = t0[(2*i+1)*LD + 2*lane];
            float b0 = t0[(2*i)*LD + 2*lane + 1];
            float b1 = t0[(2*i+1)*LD + 2*lane+1] + ((i == lane) ? sigma : 0.0f);
            A2[i] = pk2(a0, a1);
            B2[i] = pk2(b0, b1);
        }
    }

    hestenes_p(A2, B2, lane, 24, 1e-10f, 1e-9f);

    float n1, n2;
    norms_p(A2, B2, n1, n2);
    float inv1 = rsqrtf(n1), inv2 = rsqrtf(n2);
    __syncwarp();
    unpack_rows(A2, B2, t0, lane);          // t0 = W^T
    sG[2*lane]   = __expf(__fsqrt_rn(n1) - sigma) * __fdividef(1.0f, n1);
    sG[2*lane+1] = __expf(__fsqrt_rn(n2) - sigma) * __fdividef(1.0f, n2);
    __syncwarp();
    for (int k = 0; k < 64; ++k) {          // V -> g_VL
        g_VL[k*64 + 2*lane]     = t0[(2*lane)*LD + k]   * inv1;
        g_VL[k*64 + 2*lane + 1] = t0[(2*lane+1)*LD + k] * inv2;
    }
    wouter_p(A2, B2, t0, sG, lane);         // E = expm(L)
    __syncwarp();
    unpack_rows(A2, B2, t1, lane);          // t1[k][i] = E[i][k] (E symmetric)
    __syncwarp();
    ld_tile_warp(t0, g_Ms, lane);           // t0 = Ms (symmetric)
    __syncwarp();
    wgemm_p(A2, B2, t0, t1, lane);          // T = Ms * E
    __syncwarp();
    unpack_rows(A2, B2, t1, lane);          // t1[k][i] = T[i][k]
    __syncwarp();
    wgemm_p(A2, B2, t1, t0, lane);          // Mn = T * Ms
    __syncwarp();
    unpack_rows(A2, B2, t0, lane);          // t0[c][i] = Mn[i][c]
    __syncwarp();
    for (int idx = lane; idx < N*N; idx += 32) {
        int i = idx >> 6, j = idx & 63;
        g_M[idx] = 0.5f * (t0[j*LD + i] + t0[i*LD + j]);
    }
}

// C = expm(0.25 (bias + bias^T)) * invsqrtm(M);  stores C^T row-major in g_Ct
__global__ void __launch_bounds__(32) final_prep_kernel(const float* __restrict__ bias) {
    __shared__ __align__(16) float t0[TILE], t1[TILE];
    __shared__ float sG[64];
    __shared__ float s_sigma;
    const int lane = threadIdx.x;
    const unsigned FULL = 0xffffffffu;
    u64 A2[32], B2[32];

    // ---- eig(M) warm from g_VM -> Mis rows into t1 ----
    ld_tile_warp(t0, g_M, lane);
    ld_tile_warp(t1, g_VM, lane);
    __syncwarp();
    wgemm_p(A2, B2, t0, t1, lane);          // W0 = M * Vp
    hestenes_p(A2, B2, lane, 24, 1e-10f, 1e-9f);
    float n1, n2;
    norms_p(A2, B2, n1, n2);
    __syncwarp();
    unpack_rows(A2, B2, t0, lane);          // t0 = W^T
    sG[2*lane]   = __expf(-1.25f * __logf(n1));
    sG[2*lane+1] = __expf(-1.25f * __logf(n2));
    __syncwarp();
    wouter_p(A2, B2, t0, sG, lane);         // Mis columns
    __syncwarp();
    unpack_rows(A2, B2, t1, lane);          // t1[k][i] = Mis[i][k] (symmetric)
    __syncwarp();

    // ---- eig(0.25(b+b^T) + sigma I) -> Bs ----
    float fro2 = 0.0f;
    for (int idx = lane; idx < N*N; idx += 32) {
        int i = idx >> 6, j = idx & 63;
        float v = 0.25f * (bias[i*64 + j] + bias[j*64 + i]);
        t0[i*LD + j] = v;
        fro2 = fmaf(v, v, fro2);
    }
#pragma unroll
    for (int o = 16; o > 0; o >>= 1) fro2 += __shfl_down_sync(FULL, fro2, o);
    if (lane == 0) s_sigma = 1.05f * sqrtf(fro2) + 1e-12f;
    __syncwarp();
    const float sb = s_sigma;
#pragma unroll
    for (int i = 0; i < 32; ++i) {
        float a0 = t0[(2*i)*LD + 2*lane]     + ((i == lane) ? sb : 0.0f);
        float a1 = t0[(2*i+1)*LD + 2*lane];
        float b0 = t0[(2*i)*LD + 2*lane + 1];
        float b1 = t0[(2*i+1)*LD + 2*lane+1] + ((i == lane) ? sb : 0.0f);
        A2[i] = pk2(a0, a1);
        B2[i] = pk2(b0, b1);
    }
    hestenes_p(A2, B2, lane, 24, 1e-10f, 1e-9f);
    norms_p(A2, B2, n1, n2);
    __syncwarp();
    unpack_rows(A2, B2, t0, lane);          // t0 = Wb^T
    sG[2*lane]   = __expf(__fsqrt_rn(n1) - sb) * __fdividef(1.0f, n1);
    sG[2*lane+1] = __expf(__fsqrt_rn(n2) - sb) * __fdividef(1.0f, n2);
    __syncwarp();
    wouter_p(A2, B2, t0, sG, lane);         // Bs columns
    __syncwarp();
    unpack_rows(A2, B2, t0, lane);          // t0[k][i] = Bs[i][k] (symmetric)
    __syncwarp();
    wgemm_p(A2, B2, t0, t1, lane);          // C = Bs * Mis (cols 2lane, 2lane+1)
    // store C^T row-major: g_Ct[c*64 + j] = C[j][c]
    {
        u64* r0 = (u64*)&g_Ct[(2*lane)*64];
        u64* r1 = (u64*)&g_Ct[(2*lane+1)*64];
#pragma unroll
        for (int i = 0; i < 32; ++i) { r0[i] = A2[i]; r1[i] = B2[i]; }
    }
}

// ----------------------------------------------------------------------------
// Batch logm: one warp per matrix, 8 per block (256 threads — the validated
// spill-free configuration: ~212 regs/thread, L2 ~1%).
// ----------------------------------------------------------------------------
__global__ void __launch_bounds__(256) batch_log8_kernel(const float* __restrict__ data,
                                                         int warm, int store_v, int Bsz) {
    extern __shared__ __align__(16) float sm[];
    float* mis = sm;                          // 64 x LD, shared by all warps
    const int tid  = threadIdx.x;
    const int wid  = tid >> 5;
    const int lane = tid & 31;
    float* tile = sm + TILE * (1 + wid);
    float* sGw  = sm + 9*TILE + wid*64;

    {
        const float4* G4 = (const float4*)g_Mis;
        for (int idx = tid; idx < 1024; idx += 256) {
            int r = idx >> 4, c = (idx & 15) << 2;
            *(float4*)&mis[r*LD + c] = G4[idx];
        }
    }
    __syncthreads();

    const int b = blockIdx.x * 8 + wid;
    if (b >= Bsz) return;

    ld_tile_warp(tile, data + (size_t)b * (N*N), lane);   // X (symmetric)
    __syncwarp();

    u64 A2[32], B2[32];

    wgemm_p(A2, B2, tile, mis, lane);        // Z = X * Mis
    __syncwarp();
    unpack_cols(A2, B2, tile, lane);         // Z as [k][c]
    __syncwarp();
    wgemm_p(A2, B2, mis, tile, lane);        // Y = Mis * Z

    if (warm) {
        __syncwarp();
        unpack_rows(A2, B2, tile, lane);     // tile[k][i] = Y[i][k] (Y symmetric)
        __syncwarp();
        wgemm_pg(A2, B2, tile, g_Vw + (size_t)b * (N*N), lane);   // W0 = Y * Vp
    }

    hestenes_p(A2, B2, lane, 16, 1e-8f, 1e-5f);

    float n1, n2;
    norms_p(A2, B2, n1, n2);
    float inv1 = rsqrtf(n1), inv2 = rsqrtf(n2);
    __syncwarp();
    unpack_rows(A2, B2, tile, lane);         // tile = W^T
    sGw[2*lane]   = __fdividef(0.5f * __logf(n1), n1);   // log(l)/l^2
    sGw[2*lane+1] = __fdividef(0.5f * __logf(n2), n2);
    __syncwarp();

    wouter_p(A2, B2, tile, sGw, lane);       // O = W diag(g) W^T
    st_sym_global(A2, B2, g_scratch + (size_t)b * (N*N), lane);

    if (store_v) {
        float* Vd = g_Vw + (size_t)b * (N*N);
#pragma unroll
        for (int k = 0; k < 64; ++k) {
            Vd[k*64 + 2*lane]     = tile[(2*lane)*LD + k]   * inv1;
            Vd[k*64 + 2*lane + 1] = tile[(2*lane+1)*LD + k] * inv2;
        }
    }
}

// ----------------------------------------------------------------------------
// Apply: out_b = C X_b C^T (symmetric). One warp per matrix, 8 per block.
// ----------------------------------------------------------------------------
__global__ void __launch_bounds__(256) apply8_kernel(const float* __restrict__ data,
                                                     float* __restrict__ out, int Bsz) {
    extern __shared__ __align__(16) float sm[];
    float* ct = sm;                           // 64 x LD, shared by all warps
    const int tid  = threadIdx.x;
    const int wid  = tid >> 5;
    const int lane = tid & 31;
    float* tile = sm + TILE * (1 + wid);

    {
        const float4* G4 = (const float4*)g_Ct;
        for (int idx = tid; idx < 1024; idx += 256) {
            int r = idx >> 4, c = (idx & 15) << 2;
            *(float4*)&ct[r*LD + c] = G4[idx];
        }
    }
    __syncthreads();

    const int b = blockIdx.x * 8 + wid;
    if (b >= Bsz) return;

    ld_tile_warp(tile, data + (size_t)b * (N*N), lane);
    __syncwarp();

    u64 A2[32], B2[32];
    wgemm_p(A2, B2, tile, ct, lane);         // Z = X * C^T (cols 2lane, 2lane+1)
    __syncwarp();
    unpack_cols(A2, B2, tile, lane);         // Z as [k][c]
    __syncwarp();
    wgemm_p(A2, B2, ct, tile, lane);         // out = C * Z (symmetric)
    st_sym_global(A2, B2, out + (size_t)b * (N*N), lane);
}

// ----------------------------------------------------------------------------
// Host launcher (graph-capturable)
// ----------------------------------------------------------------------------
extern "C" void kernel_launch(void* const* d_in, const int* in_sizes, int n_in,
                              void* d_out, int out_size) {
    const float* data = (const float*)d_in[0];
    const float* bias = (const float*)d_in[1];
    int sz0 = in_sizes[0], sz1 = (n_in > 1) ? in_sizes[1] : 0;
    if (sz0 == N*N && sz1 > N*N) {
        data = (const float*)d_in[1];
        bias = (const float*)d_in[0];
        int t = sz0; sz0 = sz1; sz1 = t;
    }
    int Bsz = sz0 / (N*N);
    if (Bsz > MAXB) Bsz = MAXB;
    float* out = (float*)d_out;

    const size_t shmem8 = (9 * TILE + 512) * sizeof(float);     // 158,720 B
    cudaFuncSetAttribute(batch_log8_kernel, cudaFuncAttributeMaxDynamicSharedMemorySize, (int)shmem8);
    cudaFuncSetAttribute(apply8_kernel,     cudaFuncAttributeMaxDynamicSharedMemorySize, (int)shmem8);

    float *pM, *pL, *pScr, *pPart;
    cudaGetSymbolAddress((void**)&pM,    g_M);
    cudaGetSymbolAddress((void**)&pL,    g_L);
    cudaGetSymbolAddress((void**)&pScr,  g_scratch);
    cudaGetSymbolAddress((void**)&pPart, g_partial);

    const int nb1 = (Bsz + 31) / 32;
    const int nb8 = (Bsz + 7) / 8;
    const float inv = 1.0f / (float)Bsz;

    reduce32_kernel    <<<nb1, NT>>>(data, pPart, Bsz);
    reduceFinal_kernel <<<16,  NT>>>(pPart, pM, nb1, inv);

    for (int it = 0; it < 5; ++it) {
        prep_M_kernel     <<<1,   32>>>(it > 0 ? 1 : 0);
        batch_log8_kernel <<<nb8, 256, shmem8>>>(data, it > 0 ? 1 : 0, it < 4 ? 1 : 0, Bsz);
        reduce32_kernel    <<<nb1, NT>>>(pScr, pPart, Bsz);
        reduceFinal_kernel <<<16,  NT>>>(pPart, pL, nb1, inv);
        update_M_kernel   <<<1,   32>>>(it > 0 ? 1 : 0);
    }

    final_prep_kernel <<<1,   32>>>(bias);
    apply8_kernel     <<<nb8, 256, shmem8>>>(data, out, Bsz);
}